// round 3
// baseline (speedup 1.0000x reference)
#include <cuda_runtime.h>
#include <cstdint>
#include <cstddef>

#define Bn 16
#define Tn 2048
#define Dn 1024
#define Hn 512
#define Mn (Bn*Tn)      // 32768
#define Nn 3072
#define Kn 1024

// scratch (static __device__ arrays: allocation-free)
__device__ float g_Wt[(size_t)Nn * Kn];   // [n'][k], n' = plane*1024 + z*512 + h  (tf32-rounded)
__device__ float g_U [(size_t)Mn * Nn];   // [m][n'],  m = b*T + t

// ------------------------------- helpers -------------------------------
__device__ __forceinline__ uint32_t smem_u32(const void* p) {
    uint32_t a;
    asm("{ .reg .u64 t; cvta.to.shared.u64 t, %1; cvt.u32.u64 %0, t; }" : "=r"(a) : "l"(p));
    return a;
}

#define SWZ(o) ((o) ^ (((o) >> 3) & 0x70))

__device__ __forceinline__ void cp_async16(uint32_t saddr, const void* gptr) {
    asm volatile("cp.async.cg.shared.global [%0], [%1], 16;" :: "r"(saddr), "l"(gptr) : "memory");
}
__device__ __forceinline__ void cp_commit() {
    asm volatile("cp.async.commit_group;" ::: "memory");
}
template<int N> __device__ __forceinline__ void cp_wait() {
    asm volatile("cp.async.wait_group %0;" :: "n"(N) : "memory");
}

#define LDSM4(r, addr) \
    asm volatile("ldmatrix.sync.aligned.m8n8.x4.shared.b16 {%0,%1,%2,%3}, [%4];" \
        : "=r"((r)[0]), "=r"((r)[1]), "=r"((r)[2]), "=r"((r)[3]) : "r"(addr))

#define MMA_TF32(d, a, b) \
    asm volatile("mma.sync.aligned.m16n8k8.row.col.f32.tf32.tf32.f32 " \
        "{%0,%1,%2,%3}, {%4,%5,%6,%7}, {%8,%9}, {%0,%1,%2,%3};" \
        : "+f"((d)[0]), "+f"((d)[1]), "+f"((d)[2]), "+f"((d)[3]) \
        : "r"((a)[0]), "r"((a)[1]), "r"((a)[2]), "r"((a)[3]), "r"((b)[0]), "r"((b)[1]))

__device__ __forceinline__ float to_tf32_rna(float f) {
    uint32_t u;
    asm("cvt.rna.tf32.f32 %0, %1;" : "=r"(u) : "f"(f));
    return __uint_as_float(u);
}

// ------------------------- Kernel 0: W repack (tiled transpose) -------------------------
// W: (D=1024, 2, H=512, 3) row-major. g_Wt[(kk*1024 + zh)*1024 + d] = tf32(W[d*3072 + zh*3 + kk])
__global__ void __launch_bounds__(256) sru_wt(const float* __restrict__ W) {
    __shared__ float tile[32][33];
    const int tx = threadIdx.x, ty = threadIdx.y;   // 32 x 8
    const int zh0 = blockIdx.x * 32;
    const int d0  = blockIdx.y * 32;
    const int kk  = blockIdx.z;
    #pragma unroll
    for (int r = 0; r < 4; r++) {
        int d = d0 + ty + r * 8;
        int zh = zh0 + tx;
        tile[ty + r * 8][tx] = W[(size_t)d * 3072 + zh * 3 + kk];
    }
    __syncthreads();
    #pragma unroll
    for (int r = 0; r < 4; r++) {
        int zh = zh0 + ty + r * 8;
        int d  = d0 + tx;
        g_Wt[(size_t)(kk * 1024 + zh) * 1024 + d] = to_tf32_rna(tile[tx][ty + r * 8]);
    }
}

// ------------------------- Kernel 1: tf32 mma.sync GEMM -------------------------
// U[m][n'] = sum_k x[m][k] * Wt[n'][k]
#define BM 128
#define BN 256
#define BK 32
#define NCHUNK (Kn / BK)            // 32
#define ASZ (BM * BK * 4)           // 16384
#define BSZ (BN * BK * 4)           // 32768
#define STGB (ASZ + BSZ)            // 49152
#define STAGES 3
#define SMEM_TOTAL (STAGES * STGB)  // 147456

__global__ void __launch_bounds__(512, 1) sru_gemm(const float* __restrict__ x) {
    extern __shared__ __align__(1024) char smem[];
    const uint32_t sb = smem_u32(smem);
    const int tid = threadIdx.x;
    const int lane = tid & 31;
    const int w = tid >> 5;                 // 0..15
    const int m0 = blockIdx.y * BM;
    const int n0 = blockIdx.x * BN;
    const int wm = (w & 3) * 32;            // warp m offset in tile
    const int wn = (w >> 2) * 64;           // warp n offset in tile

    // ---- cp.async geometry: 16B segments, thread t: row r=t>>3, seg=t&7 ----
    const int rr  = tid >> 3;   // 0..63
    const int seg = tid & 7;    // 0..7
    const float* aS = x    + (size_t)(m0 + rr) * Kn + seg * 4;
    const float* bS = g_Wt + (size_t)(n0 + rr) * Kn + seg * 4;
    uint32_t aO[2], bO[4];
    #pragma unroll
    for (int j = 0; j < 2; j++) { uint32_t o = (uint32_t)(rr + 64 * j) * 128 + seg * 16; aO[j] = SWZ(o); }
    #pragma unroll
    for (int j = 0; j < 4; j++) { uint32_t o = (uint32_t)(rr + 64 * j) * 128 + seg * 16; bO[j] = ASZ + SWZ(o); }

    auto ldchunk = [&](int c, int s) {
        uint32_t st = sb + (uint32_t)s * STGB;
        const float* ap = aS + c * BK;
        const float* bp = bS + c * BK;
        #pragma unroll
        for (int j = 0; j < 2; j++) cp_async16(st + aO[j], ap + (size_t)(64 * j) * Kn);
        #pragma unroll
        for (int j = 0; j < 4; j++) cp_async16(st + bO[j], bp + (size_t)(64 * j) * Kn);
        cp_commit();
    };

    // ---- ldmatrix per-lane address precompute ----
    // A frags (m16n8k8 A): tiles (r0-7,k0-3)(r8-15,k0-3)(r0-7,k4-7)(r8-15,k4-7)
    uint32_t aRow[2], aXor[2];
    #pragma unroll
    for (int mi = 0; mi < 2; mi++) {
        uint32_t r = wm + mi * 16 + ((lane & 8) ? 8 : 0) + (lane & 7);
        aRow[mi] = r * 128; aXor[mi] = (r & 7) << 4;
    }
    const uint32_t aHi = (lane & 16) ? 16 : 0;
    // B frags: pair p covers n rows p*16..p*16+15; tiles (n0-7,k0-3)(n0-7,k4-7)(n8-15,k0-3)(n8-15,k4-7)
    uint32_t bRow[4], bXor[4];
    #pragma unroll
    for (int p = 0; p < 4; p++) {
        uint32_t r = wn + p * 16 + ((lane & 16) ? 8 : 0) + (lane & 7);
        bRow[p] = ASZ + r * 128; bXor[p] = (r & 7) << 4;
    }
    const uint32_t bHi = (lane & 8) ? 16 : 0;

    float acc[2][8][4];
    #pragma unroll
    for (int mi = 0; mi < 2; mi++)
        #pragma unroll
        for (int nj = 0; nj < 8; nj++)
            #pragma unroll
            for (int q = 0; q < 4; q++) acc[mi][nj][q] = 0.f;

    ldchunk(0, 0);
    ldchunk(1, 1);

    for (int i = 0; i < NCHUNK; i++) {
        int s = i % 3;
        if (i + 2 < NCHUNK) ldchunk(i + 2, (i + 2) % 3);
        if (i < NCHUNK - 2)       cp_wait<2>();
        else if (i == NCHUNK - 2) cp_wait<1>();
        else                      cp_wait<0>();
        __syncthreads();

        uint32_t st = sb + (uint32_t)s * STGB;
        #pragma unroll
        for (int ks = 0; ks < 4; ks++) {
            uint32_t koff = ks * 32;
            uint32_t ar[2][4], br[4][4];
            #pragma unroll
            for (int mi = 0; mi < 2; mi++)
                LDSM4(ar[mi], st + aRow[mi] + ((koff + aHi) ^ aXor[mi]));
            #pragma unroll
            for (int p = 0; p < 4; p++)
                LDSM4(br[p], st + bRow[p] + ((koff + bHi) ^ bXor[p]));
            #pragma unroll
            for (int mi = 0; mi < 2; mi++)
                #pragma unroll
                for (int nj = 0; nj < 8; nj++)
                    MMA_TF32(acc[mi][nj], ar[mi], &br[nj >> 1][(nj & 1) * 2]);
        }
        __syncthreads();
    }

    // ---- epilogue: direct fp32 stores (full 32B sectors) ----
    const int rowb = m0 + wm + (lane >> 2);
    const int colb = n0 + wn + (lane & 3) * 2;
    #pragma unroll
    for (int mi = 0; mi < 2; mi++)
        #pragma unroll
        for (int nj = 0; nj < 8; nj++) {
            size_t base = (size_t)(rowb + mi * 16) * Nn + colb + nj * 8;
            float2 v0 = make_float2(acc[mi][nj][0], acc[mi][nj][1]);
            float2 v1 = make_float2(acc[mi][nj][2], acc[mi][nj][3]);
            *(float2*)(g_U + base) = v0;
            *(float2*)(g_U + base + 8 * (size_t)Nn) = v1;
        }
}

// ------------------------------- Kernel 2: SRU scan -------------------------------
__device__ __forceinline__ void scan_load(const float*& pU, const float*& pX, long us, long xs,
    float (&G)[8], float (&F)[8], float (&R)[8], float (&X)[8]) {
    #pragma unroll
    for (int k = 0; k < 8; k++) {
        G[k] = pU[0]; F[k] = pU[1024]; R[k] = pU[2048]; X[k] = pX[0];
        pU += us; pX += xs;
    }
}

__device__ __forceinline__ void scan_comp(float& c, float bf, float br, float*& pO, long xs,
    const float (&G)[8], const float (&F)[8], const float (&R)[8], const float (&X)[8]) {
    float fv[8], cc[8];
    #pragma unroll
    for (int k = 0; k < 8; k++) {
        float e = __expf(-(F[k] + bf));
        fv[k] = __fdividef(1.f, 1.f + e);
    }
    #pragma unroll
    for (int k = 0; k < 8; k++) {       // c = f*c + (1-f)*g  (serial FMA chain)
        c = fv[k] * (c - G[k]) + G[k];
        cc[k] = c;
    }
    #pragma unroll
    for (int k = 0; k < 8; k++) {       // h = r*tanh(c) + (1-r)*x  (ILP-8)
        float e2 = __expf(-(R[k] + br));
        float rv = __fdividef(1.f, 1.f + e2);
        float eT = __expf(2.f * cc[k]);
        float th = 1.f - 2.f * __fdividef(1.f, 1.f + eT);
        pO[0] = rv * (th - X[k]) + X[k];
        pO += xs;
    }
}

__global__ void __launch_bounds__(256) sru_scan(const float* __restrict__ x,
                                                const float* __restrict__ bias,
                                                float* __restrict__ out) {
    int t = blockIdx.x * 256 + threadIdx.x;     // 0..16383
    int h = t & (Hn - 1);
    int z = (t >> 9) & 1;
    int b = t >> 10;
    const float bf = bias[z * 1024 + h];            // bias[z][0][h]
    const float br = bias[z * 1024 + 512 + h];      // bias[z][1][h]
    const int fwd = (z == 0);
    const long us = fwd ? (long)Nn : -(long)Nn;
    const long xs = fwd ? 1024L : -1024L;
    const float* pU = g_U + (size_t)b * Tn * Nn + z * Hn + h + (fwd ? 0 : (size_t)(Tn - 1) * Nn);
    const float* pX = x   + (size_t)b * Tn * Dn + z * Hn + h + (fwd ? 0 : (size_t)(Tn - 1) * Dn);
    float*       pO = out + (size_t)b * Tn * Dn + z * Hn + h + (fwd ? 0 : (size_t)(Tn - 1) * Dn);

    float c = 0.f;
    float gA[8], fA[8], rA[8], xA[8], gB[8], fB[8], rB[8], xB[8];

    scan_load(pU, pX, us, xs, gA, fA, rA, xA);                  // group 0
    for (int grp = 0; grp < 256; grp += 2) {
        scan_load(pU, pX, us, xs, gB, fB, rB, xB);              // group grp+1
        scan_comp(c, bf, br, pO, xs, gA, fA, rA, xA);           // group grp
        if (grp + 2 < 256)
            scan_load(pU, pX, us, xs, gA, fA, rA, xA);          // group grp+2
        scan_comp(c, bf, br, pO, xs, gB, fB, rB, xB);           // group grp+1
    }
    // c_last: (B, 1, 2H) appended after out
    out[(size_t)Bn * Tn * 1024 + (size_t)b * 1024 + z * 512 + h] = c;
}

// ------------------------------- launch -------------------------------
extern "C" void kernel_launch(void* const* d_in, const int* in_sizes, int n_in,
                              void* d_out, int out_size) {
    const float* x    = (const float*)d_in[0];
    const float* W    = (const float*)d_in[1];
    const float* bias = (const float*)d_in[2];
    float* out = (float*)d_out;
    (void)in_sizes; (void)n_in; (void)out_size;

    cudaFuncSetAttribute(sru_gemm, cudaFuncAttributeMaxDynamicSharedMemorySize, SMEM_TOTAL);

    sru_wt  <<<dim3(32, 32, 3), dim3(32, 8)>>>(W);
    sru_gemm<<<dim3(Nn / BN, Mn / BM), 512, SMEM_TOTAL>>>(x);
    sru_scan<<<(Bn * 2 * Hn) / 256, 256>>>(x, bias, out);
}

// round 4
// speedup vs baseline: 1.0540x; 1.0540x over previous
#include <cuda_runtime.h>
#include <cstdint>
#include <cstddef>

#define Bn 16
#define Tn 2048
#define Dn 1024
#define Hn 512
#define Mn (Bn*Tn)      // 32768
#define Nn 3072
#define Kn 1024

// scratch (static __device__ arrays: allocation-free)
__device__ float g_Wt[(size_t)Nn * Kn];   // [n'][k], n' = plane*1024 + z*512 + h  (tf32-rounded)
__device__ float g_U [(size_t)Mn * Nn];   // [m][n'],  m = b*T + t

// ------------------------------- helpers -------------------------------
__device__ __forceinline__ uint32_t smem_u32(const void* p) {
    uint32_t a;
    asm("{ .reg .u64 t; cvta.to.shared.u64 t, %1; cvt.u32.u64 %0, t; }" : "=r"(a) : "l"(p));
    return a;
}

#define SWZ(o) ((o) ^ (((o) >> 3) & 0x70))

__device__ __forceinline__ void cp_async16(uint32_t saddr, const void* gptr) {
    asm volatile("cp.async.cg.shared.global [%0], [%1], 16;" :: "r"(saddr), "l"(gptr) : "memory");
}
__device__ __forceinline__ void cp_commit() {
    asm volatile("cp.async.commit_group;" ::: "memory");
}
template<int N> __device__ __forceinline__ void cp_wait() {
    asm volatile("cp.async.wait_group %0;" :: "n"(N) : "memory");
}

#define LDSM4(r, addr) \
    asm volatile("ldmatrix.sync.aligned.m8n8.x4.shared.b16 {%0,%1,%2,%3}, [%4];" \
        : "=r"((r)[0]), "=r"((r)[1]), "=r"((r)[2]), "=r"((r)[3]) : "r"(addr))

#define MMA_TF32(d, a, b) \
    asm volatile("mma.sync.aligned.m16n8k8.row.col.f32.tf32.tf32.f32 " \
        "{%0,%1,%2,%3}, {%4,%5,%6,%7}, {%8,%9}, {%0,%1,%2,%3};" \
        : "+f"((d)[0]), "+f"((d)[1]), "+f"((d)[2]), "+f"((d)[3]) \
        : "r"((a)[0]), "r"((a)[1]), "r"((a)[2]), "r"((a)[3]), "r"((b)[0]), "r"((b)[1]))

__device__ __forceinline__ float to_tf32_rna(float f) {
    uint32_t u;
    asm("cvt.rna.tf32.f32 %0, %1;" : "=r"(u) : "f"(f));
    return __uint_as_float(u);
}

// ------------------------- Kernel 0: W repack (tiled transpose) -------------------------
// W: (D=1024, 2, H=512, 3) row-major. g_Wt[(kk*1024 + zh)*1024 + d] = tf32(W[d*3072 + zh*3 + kk])
__global__ void __launch_bounds__(256) sru_wt(const float* __restrict__ W) {
    __shared__ float tile[32][33];
    const int tx = threadIdx.x, ty = threadIdx.y;   // 32 x 8
    const int zh0 = blockIdx.x * 32;
    const int d0  = blockIdx.y * 32;
    const int kk  = blockIdx.z;
    #pragma unroll
    for (int r = 0; r < 4; r++) {
        int d = d0 + ty + r * 8;
        int zh = zh0 + tx;
        tile[ty + r * 8][tx] = W[(size_t)d * 3072 + zh * 3 + kk];
    }
    __syncthreads();
    #pragma unroll
    for (int r = 0; r < 4; r++) {
        int zh = zh0 + ty + r * 8;
        int d  = d0 + tx;
        g_Wt[(size_t)(kk * 1024 + zh) * 1024 + d] = to_tf32_rna(tile[tx][ty + r * 8]);
    }
}

// ------------------------- Kernel 1: tf32 mma.sync GEMM -------------------------
// U[m][n'] = sum_k x[m][k] * Wt[n'][k]
// 256 threads, 8 warps (2m x 4n), warp tile 64x64, 4-stage cp.async, 1 sync/chunk
#define BM 128
#define BN 256
#define BK 32
#define NCHUNK (Kn / BK)            // 32
#define ASZ (BM * BK * 4)           // 16384
#define BSZ (BN * BK * 4)           // 32768
#define STGB (ASZ + BSZ)            // 49152
#define STAGES 4
#define SMEM_TOTAL (STAGES * STGB)  // 196608

__global__ void __launch_bounds__(256, 1) sru_gemm(const float* __restrict__ x) {
    extern __shared__ __align__(1024) char smem[];
    const uint32_t sb = smem_u32(smem);
    const int tid = threadIdx.x;
    const int lane = tid & 31;
    const int w = tid >> 5;                 // 0..7
    const int m0 = blockIdx.y * BM;
    const int n0 = blockIdx.x * BN;
    const int wm = (w & 1) * 64;            // warp m offset in tile
    const int wn = (w >> 1) * 64;           // warp n offset in tile

    // ---- cp.async geometry: 16B segments; row rr = tid>>3 (+32j), seg = tid&7 ----
    const int rr  = tid >> 3;   // 0..31
    const int seg = tid & 7;    // 0..7
    const float* aS = x    + (size_t)(m0 + rr) * Kn + seg * 4;
    const float* bS = g_Wt + (size_t)(n0 + rr) * Kn + seg * 4;
    uint32_t aO[4], bO[8];
    #pragma unroll
    for (int j = 0; j < 4; j++) { uint32_t o = (uint32_t)(rr + 32 * j) * 128 + seg * 16; aO[j] = SWZ(o); }
    #pragma unroll
    for (int j = 0; j < 8; j++) { uint32_t o = (uint32_t)(rr + 32 * j) * 128 + seg * 16; bO[j] = ASZ + SWZ(o); }

    auto ldchunk = [&](int c, int s) {
        uint32_t st = sb + (uint32_t)s * STGB;
        const float* ap = aS + c * BK;
        const float* bp = bS + c * BK;
        #pragma unroll
        for (int j = 0; j < 4; j++) cp_async16(st + aO[j], ap + (size_t)(32 * j) * Kn);
        #pragma unroll
        for (int j = 0; j < 8; j++) cp_async16(st + bO[j], bp + (size_t)(32 * j) * Kn);
        cp_commit();
    };

    // ---- ldmatrix per-lane address precompute (validated in R3) ----
    uint32_t aRow[4], aXor[4];
    #pragma unroll
    for (int mi = 0; mi < 4; mi++) {
        uint32_t r = wm + mi * 16 + ((lane & 8) ? 8 : 0) + (lane & 7);
        aRow[mi] = r * 128; aXor[mi] = (r & 7) << 4;
    }
    const uint32_t aHi = (lane & 16) ? 16 : 0;
    uint32_t bRow[4], bXor[4];
    #pragma unroll
    for (int p = 0; p < 4; p++) {
        uint32_t r = wn + p * 16 + ((lane & 16) ? 8 : 0) + (lane & 7);
        bRow[p] = ASZ + r * 128; bXor[p] = (r & 7) << 4;
    }
    const uint32_t bHi = (lane & 8) ? 16 : 0;

    float acc[4][8][4];
    #pragma unroll
    for (int mi = 0; mi < 4; mi++)
        #pragma unroll
        for (int nj = 0; nj < 8; nj++)
            #pragma unroll
            for (int q = 0; q < 4; q++) acc[mi][nj][q] = 0.f;

    // prologue: chunks 0,1 into stages 0,1 (prefetch depth 2)
    ldchunk(0, 0);
    ldchunk(1, 1);

    for (int i = 0; i < NCHUNK; i++) {
        if (i + 2 < NCHUNK) ldchunk(i + 2, (i + 2) & 3);
        else                cp_commit();            // empty group keeps wait-count uniform
        cp_wait<2>();
        __syncthreads();

        uint32_t st = sb + (uint32_t)(i & 3) * STGB;
        #pragma unroll
        for (int ks = 0; ks < 4; ks++) {
            uint32_t koff = ks * 32;
            uint32_t ar[4][4], br[4][4];
            #pragma unroll
            for (int mi = 0; mi < 4; mi++)
                LDSM4(ar[mi], st + aRow[mi] + ((koff + aHi) ^ aXor[mi]));
            #pragma unroll
            for (int p = 0; p < 4; p++)
                LDSM4(br[p], st + bRow[p] + ((koff + bHi) ^ bXor[p]));
            #pragma unroll
            for (int mi = 0; mi < 4; mi++)
                #pragma unroll
                for (int nj = 0; nj < 8; nj++)
                    MMA_TF32(acc[mi][nj], ar[mi], &br[nj >> 1][(nj & 1) * 2]);
        }
        // no trailing sync: next iteration writes stage (i+3)&3 != i&3
    }

    // ---- epilogue: direct fp32 stores ----
    const int rowb = m0 + wm + (lane >> 2);
    const int colb = n0 + wn + (lane & 3) * 2;
    #pragma unroll
    for (int mi = 0; mi < 4; mi++)
        #pragma unroll
        for (int nj = 0; nj < 8; nj++) {
            size_t base = (size_t)(rowb + mi * 16) * Nn + colb + nj * 8;
            float2 v0 = make_float2(acc[mi][nj][0], acc[mi][nj][1]);
            float2 v1 = make_float2(acc[mi][nj][2], acc[mi][nj][3]);
            *(float2*)(g_U + base) = v0;
            *(float2*)(g_U + base + 8 * (size_t)Nn) = v1;
        }
}

// ------------------------------- Kernel 2: SRU scan -------------------------------
__device__ __forceinline__ void scan_load(const float*& pU, const float*& pX, long us, long xs,
    float (&G)[8], float (&F)[8], float (&R)[8], float (&X)[8]) {
    #pragma unroll
    for (int k = 0; k < 8; k++) {
        G[k] = pU[0]; F[k] = pU[1024]; R[k] = pU[2048]; X[k] = pX[0];
        pU += us; pX += xs;
    }
}

__device__ __forceinline__ void scan_comp(float& c, float bf, float br, float*& pO, long xs,
    const float (&G)[8], const float (&F)[8], const float (&R)[8], const float (&X)[8]) {
    float fv[8], cc[8];
    #pragma unroll
    for (int k = 0; k < 8; k++) {
        float e = __expf(-(F[k] + bf));
        fv[k] = __fdividef(1.f, 1.f + e);
    }
    #pragma unroll
    for (int k = 0; k < 8; k++) {       // c = f*c + (1-f)*g  (serial FMA chain)
        c = fv[k] * (c - G[k]) + G[k];
        cc[k] = c;
    }
    #pragma unroll
    for (int k = 0; k < 8; k++) {       // h = r*tanh(c) + (1-r)*x  (ILP-8)
        float e2 = __expf(-(R[k] + br));
        float rv = __fdividef(1.f, 1.f + e2);
        float eT = __expf(2.f * cc[k]);
        float th = 1.f - 2.f * __fdividef(1.f, 1.f + eT);
        pO[0] = rv * (th - X[k]) + X[k];
        pO += xs;
    }
}

__global__ void __launch_bounds__(256) sru_scan(const float* __restrict__ x,
                                                const float* __restrict__ bias,
                                                float* __restrict__ out) {
    int t = blockIdx.x * 256 + threadIdx.x;     // 0..16383
    int h = t & (Hn - 1);
    int z = (t >> 9) & 1;
    int b = t >> 10;
    const float bf = bias[z * 1024 + h];            // bias[z][0][h]
    const float br = bias[z * 1024 + 512 + h];      // bias[z][1][h]
    const int fwd = (z == 0);
    const long us = fwd ? (long)Nn : -(long)Nn;
    const long xs = fwd ? 1024L : -1024L;
    const float* pU = g_U + (size_t)b * Tn * Nn + z * Hn + h + (fwd ? 0 : (size_t)(Tn - 1) * Nn);
    const float* pX = x   + (size_t)b * Tn * Dn + z * Hn + h + (fwd ? 0 : (size_t)(Tn - 1) * Dn);
    float*       pO = out + (size_t)b * Tn * Dn + z * Hn + h + (fwd ? 0 : (size_t)(Tn - 1) * Dn);

    float c = 0.f;
    float gA[8], fA[8], rA[8], xA[8], gB[8], fB[8], rB[8], xB[8];

    scan_load(pU, pX, us, xs, gA, fA, rA, xA);                  // group 0
    for (int grp = 0; grp < 256; grp += 2) {
        scan_load(pU, pX, us, xs, gB, fB, rB, xB);              // group grp+1
        scan_comp(c, bf, br, pO, xs, gA, fA, rA, xA);           // group grp
        if (grp + 2 < 256)
            scan_load(pU, pX, us, xs, gA, fA, rA, xA);          // group grp+2
        scan_comp(c, bf, br, pO, xs, gB, fB, rB, xB);           // group grp+1
    }
    // c_last: (B, 1, 2H) appended after out
    out[(size_t)Bn * Tn * 1024 + (size_t)b * 1024 + z * 512 + h] = c;
}

// ------------------------------- launch -------------------------------
extern "C" void kernel_launch(void* const* d_in, const int* in_sizes, int n_in,
                              void* d_out, int out_size) {
    const float* x    = (const float*)d_in[0];
    const float* W    = (const float*)d_in[1];
    const float* bias = (const float*)d_in[2];
    float* out = (float*)d_out;
    (void)in_sizes; (void)n_in; (void)out_size;

    cudaFuncSetAttribute(sru_gemm, cudaFuncAttributeMaxDynamicSharedMemorySize, SMEM_TOTAL);

    sru_wt  <<<dim3(32, 32, 3), dim3(32, 8)>>>(W);
    sru_gemm<<<dim3(Nn / BN, Mn / BM), 256, SMEM_TOTAL>>>(x);
    sru_scan<<<(Bn * 2 * Hn) / 256, 256>>>(x, bias, out);
}

// round 5
// speedup vs baseline: 1.5623x; 1.4822x over previous
#include <cuda_runtime.h>
#include <cuda_fp16.h>
#include <cstdint>
#include <cstddef>

#define Bn 16
#define Tn 2048
#define Dn 1024
#define Hn 512
#define Mn (Bn*Tn)      // 32768
#define Nn 3072
#define Kn 1024

// scratch (static __device__ arrays: allocation-free)
__device__ __half g_Wt[(size_t)Nn * Kn];  // [n'][k], n' = plane*1024 + z*512 + h  (fp16)
__device__ __half g_xh[(size_t)Mn * Kn];  // x in fp16
__device__ float  g_U [(size_t)Mn * Nn];  // [m][n'],  m = b*T + t

// ------------------------------- helpers -------------------------------
__device__ __forceinline__ uint32_t smem_u32(const void* p) {
    uint32_t a;
    asm("{ .reg .u64 t; cvta.to.shared.u64 t, %1; cvt.u32.u64 %0, t; }" : "=r"(a) : "l"(p));
    return a;
}

#define SWZ(o) ((o) ^ (((o) >> 3) & 0x70))

__device__ __forceinline__ void cp_async16(uint32_t saddr, const void* gptr) {
    asm volatile("cp.async.cg.shared.global [%0], [%1], 16;" :: "r"(saddr), "l"(gptr) : "memory");
}
__device__ __forceinline__ void cp_commit() {
    asm volatile("cp.async.commit_group;" ::: "memory");
}
template<int N> __device__ __forceinline__ void cp_wait() {
    asm volatile("cp.async.wait_group %0;" :: "n"(N) : "memory");
}

#define LDSM4(r, addr) \
    asm volatile("ldmatrix.sync.aligned.m8n8.x4.shared.b16 {%0,%1,%2,%3}, [%4];" \
        : "=r"((r)[0]), "=r"((r)[1]), "=r"((r)[2]), "=r"((r)[3]) : "r"(addr))

#define MMA_F16(d, a, b) \
    asm volatile("mma.sync.aligned.m16n8k16.row.col.f32.f16.f16.f32 " \
        "{%0,%1,%2,%3}, {%4,%5,%6,%7}, {%8,%9}, {%0,%1,%2,%3};" \
        : "+f"((d)[0]), "+f"((d)[1]), "+f"((d)[2]), "+f"((d)[3]) \
        : "r"((a)[0]), "r"((a)[1]), "r"((a)[2]), "r"((a)[3]), "r"((b)[0]), "r"((b)[1]))

// ------------------------- Kernel 0a: x -> fp16 -------------------------
__global__ void __launch_bounds__(256) sru_xh(const float* __restrict__ x) {
    size_t i = (size_t)blockIdx.x * 256 + threadIdx.x;
    float4 v = ((const float4*)x)[i];
    __half2* o = (__half2*)g_xh + i * 2;
    o[0] = __floats2half2_rn(v.x, v.y);
    o[1] = __floats2half2_rn(v.z, v.w);
}

// ------------------------- Kernel 0b: W repack (tiled transpose, fp16) -------------------------
// W: (D=1024, 2, H=512, 3) row-major. g_Wt[(kk*1024 + zh)*1024 + d] = h(W[d*3072 + zh*3 + kk])
__global__ void __launch_bounds__(256) sru_wt(const float* __restrict__ W) {
    __shared__ float tile[32][33];
    const int tx = threadIdx.x, ty = threadIdx.y;   // 32 x 8
    const int zh0 = blockIdx.x * 32;
    const int d0  = blockIdx.y * 32;
    const int kk  = blockIdx.z;
    #pragma unroll
    for (int r = 0; r < 4; r++) {
        int d = d0 + ty + r * 8;
        int zh = zh0 + tx;
        tile[ty + r * 8][tx] = W[(size_t)d * 3072 + zh * 3 + kk];
    }
    __syncthreads();
    #pragma unroll
    for (int r = 0; r < 4; r++) {
        int zh = zh0 + ty + r * 8;
        int d  = d0 + tx;
        g_Wt[(size_t)(kk * 1024 + zh) * 1024 + d] = __float2half_rn(tile[tx][ty + r * 8]);
    }
}

// ------------------------- Kernel 1: fp16 mma.sync GEMM (fp32 accum) -------------------------
// U[m][n'] = sum_k x[m][k] * Wt[n'][k]
// 256 threads, 8 warps (2m x 4n), warp tile 64x64, BK=64 halfs (128B rows), 4-stage, 1 sync/chunk
#define BM 128
#define BN 256
#define BK 64
#define NCHUNK (Kn / BK)            // 16
#define ASZ (BM * 128)              // 16384 bytes
#define BSZ (BN * 128)              // 32768 bytes
#define STGB (ASZ + BSZ)            // 49152
#define STAGES 4
#define SMEM_TOTAL (STAGES * STGB)  // 196608

__global__ void __launch_bounds__(256, 1) sru_gemm() {
    extern __shared__ __align__(1024) char smem[];
    const uint32_t sb = smem_u32(smem);
    const int tid = threadIdx.x;
    const int lane = tid & 31;
    const int w = tid >> 5;                 // 0..7
    const int m0 = blockIdx.y * BM;
    const int n0 = blockIdx.x * BN;
    const int wm = (w & 1) * 64;            // warp m offset in tile
    const int wn = (w >> 1) * 64;           // warp n offset in tile

    // ---- cp.async geometry: 16B segments (8 halfs); row rr = tid>>3 (+32j), seg = tid&7 ----
    const int rr  = tid >> 3;   // 0..31
    const int seg = tid & 7;    // 0..7
    const __half* aS = g_xh + (size_t)(m0 + rr) * Kn + seg * 8;
    const __half* bS = g_Wt + (size_t)(n0 + rr) * Kn + seg * 8;
    uint32_t aO[4], bO[8];
    #pragma unroll
    for (int j = 0; j < 4; j++) { uint32_t o = (uint32_t)(rr + 32 * j) * 128 + seg * 16; aO[j] = SWZ(o); }
    #pragma unroll
    for (int j = 0; j < 8; j++) { uint32_t o = (uint32_t)(rr + 32 * j) * 128 + seg * 16; bO[j] = ASZ + SWZ(o); }

    auto ldchunk = [&](int c, int s) {
        uint32_t st = sb + (uint32_t)s * STGB;
        const __half* ap = aS + c * BK;
        const __half* bp = bS + c * BK;
        #pragma unroll
        for (int j = 0; j < 4; j++) cp_async16(st + aO[j], ap + (size_t)(32 * j) * Kn);
        #pragma unroll
        for (int j = 0; j < 8; j++) cp_async16(st + bO[j], bp + (size_t)(32 * j) * Kn);
        cp_commit();
    };

    // ---- ldmatrix per-lane addresses (same byte math as validated tf32 version) ----
    uint32_t aRow[4], aXor[4];
    #pragma unroll
    for (int mi = 0; mi < 4; mi++) {
        uint32_t r = wm + mi * 16 + ((lane & 8) ? 8 : 0) + (lane & 7);
        aRow[mi] = r * 128; aXor[mi] = (r & 7) << 4;
    }
    const uint32_t aHi = (lane & 16) ? 16 : 0;
    uint32_t bRow[4], bXor[4];
    #pragma unroll
    for (int p = 0; p < 4; p++) {
        uint32_t r = wn + p * 16 + ((lane & 16) ? 8 : 0) + (lane & 7);
        bRow[p] = ASZ + r * 128; bXor[p] = (r & 7) << 4;
    }
    const uint32_t bHi = (lane & 8) ? 16 : 0;

    float acc[4][8][4];
    #pragma unroll
    for (int mi = 0; mi < 4; mi++)
        #pragma unroll
        for (int nj = 0; nj < 8; nj++)
            #pragma unroll
            for (int q = 0; q < 4; q++) acc[mi][nj][q] = 0.f;

    ldchunk(0, 0);
    ldchunk(1, 1);

    for (int i = 0; i < NCHUNK; i++) {
        if (i + 2 < NCHUNK) ldchunk(i + 2, (i + 2) & 3);
        else                cp_commit();            // empty group keeps wait-count uniform
        cp_wait<2>();
        __syncthreads();

        uint32_t st = sb + (uint32_t)(i & 3) * STGB;
        #pragma unroll
        for (int ks = 0; ks < 4; ks++) {            // k16 slice = 32 bytes
            uint32_t koff = ks * 32;
            uint32_t ar[4][4], br[4][4];
            #pragma unroll
            for (int mi = 0; mi < 4; mi++)
                LDSM4(ar[mi], st + aRow[mi] + ((koff + aHi) ^ aXor[mi]));
            #pragma unroll
            for (int p = 0; p < 4; p++)
                LDSM4(br[p], st + bRow[p] + ((koff + bHi) ^ bXor[p]));
            #pragma unroll
            for (int mi = 0; mi < 4; mi++)
                #pragma unroll
                for (int nj = 0; nj < 8; nj++)
                    MMA_F16(acc[mi][nj], ar[mi], &br[nj >> 1][(nj & 1) * 2]);
        }
        // no trailing sync: next iteration writes stage (i+3)&3 != i&3
    }

    // ---- epilogue: direct fp32 stores ----
    const int rowb = m0 + wm + (lane >> 2);
    const int colb = n0 + wn + (lane & 3) * 2;
    #pragma unroll
    for (int mi = 0; mi < 4; mi++)
        #pragma unroll
        for (int nj = 0; nj < 8; nj++) {
            size_t base = (size_t)(rowb + mi * 16) * Nn + colb + nj * 8;
            float2 v0 = make_float2(acc[mi][nj][0], acc[mi][nj][1]);
            float2 v1 = make_float2(acc[mi][nj][2], acc[mi][nj][3]);
            *(float2*)(g_U + base) = v0;
            *(float2*)(g_U + base + 8 * (size_t)Nn) = v1;
        }
}

// ------------------------------- Kernel 2: SRU scan -------------------------------
__device__ __forceinline__ void scan_load(const float*& pU, const float*& pX, long us, long xs,
    float (&G)[8], float (&F)[8], float (&R)[8], float (&X)[8]) {
    #pragma unroll
    for (int k = 0; k < 8; k++) {
        G[k] = pU[0]; F[k] = pU[1024]; R[k] = pU[2048]; X[k] = pX[0];
        pU += us; pX += xs;
    }
}

__device__ __forceinline__ void scan_comp(float& c, float bf, float br, float*& pO, long xs,
    const float (&G)[8], const float (&F)[8], const float (&R)[8], const float (&X)[8]) {
    float fv[8], cc[8];
    #pragma unroll
    for (int k = 0; k < 8; k++) {
        float e = __expf(-(F[k] + bf));
        fv[k] = __fdividef(1.f, 1.f + e);
    }
    #pragma unroll
    for (int k = 0; k < 8; k++) {       // c = f*c + (1-f)*g  (serial FMA chain)
        c = fv[k] * (c - G[k]) + G[k];
        cc[k] = c;
    }
    #pragma unroll
    for (int k = 0; k < 8; k++) {       // h = r*tanh(c) + (1-r)*x  (ILP-8)
        float e2 = __expf(-(R[k] + br));
        float rv = __fdividef(1.f, 1.f + e2);
        float eT = __expf(2.f * cc[k]);
        float th = 1.f - 2.f * __fdividef(1.f, 1.f + eT);
        pO[0] = rv * (th - X[k]) + X[k];
        pO += xs;
    }
}

__global__ void __launch_bounds__(256) sru_scan(const float* __restrict__ x,
                                                const float* __restrict__ bias,
                                                float* __restrict__ out) {
    int t = blockIdx.x * 256 + threadIdx.x;     // 0..16383
    int h = t & (Hn - 1);
    int z = (t >> 9) & 1;
    int b = t >> 10;
    const float bf = bias[z * 1024 + h];            // bias[z][0][h]
    const float br = bias[z * 1024 + 512 + h];      // bias[z][1][h]
    const int fwd = (z == 0);
    const long us = fwd ? (long)Nn : -(long)Nn;
    const long xs = fwd ? 1024L : -1024L;
    const float* pU = g_U + (size_t)b * Tn * Nn + z * Hn + h + (fwd ? 0 : (size_t)(Tn - 1) * Nn);
    const float* pX = x   + (size_t)b * Tn * Dn + z * Hn + h + (fwd ? 0 : (size_t)(Tn - 1) * Dn);
    float*       pO = out + (size_t)b * Tn * Dn + z * Hn + h + (fwd ? 0 : (size_t)(Tn - 1) * Dn);

    float c = 0.f;
    float gA[8], fA[8], rA[8], xA[8], gB[8], fB[8], rB[8], xB[8];

    scan_load(pU, pX, us, xs, gA, fA, rA, xA);                  // group 0
    for (int grp = 0; grp < 256; grp += 2) {
        scan_load(pU, pX, us, xs, gB, fB, rB, xB);              // group grp+1
        scan_comp(c, bf, br, pO, xs, gA, fA, rA, xA);           // group grp
        if (grp + 2 < 256)
            scan_load(pU, pX, us, xs, gA, fA, rA, xA);          // group grp+2
        scan_comp(c, bf, br, pO, xs, gB, fB, rB, xB);           // group grp+1
    }
    // c_last: (B, 1, 2H) appended after out
    out[(size_t)Bn * Tn * 1024 + (size_t)b * 1024 + z * 512 + h] = c;
}

// ------------------------------- launch -------------------------------
extern "C" void kernel_launch(void* const* d_in, const int* in_sizes, int n_in,
                              void* d_out, int out_size) {
    const float* x    = (const float*)d_in[0];
    const float* W    = (const float*)d_in[1];
    const float* bias = (const float*)d_in[2];
    float* out = (float*)d_out;
    (void)in_sizes; (void)n_in; (void)out_size;

    cudaFuncSetAttribute(sru_gemm, cudaFuncAttributeMaxDynamicSharedMemorySize, SMEM_TOTAL);

    sru_xh  <<<(Mn * (Kn / 4)) / 256, 256>>>(x);
    sru_wt  <<<dim3(32, 32, 3), dim3(32, 8)>>>(W);
    sru_gemm<<<dim3(Nn / BN, Mn / BM), 256, SMEM_TOTAL>>>();
    sru_scan<<<(Bn * 2 * Hn) / 256, 256>>>(x, bias, out);
}

// round 6
// speedup vs baseline: 1.6242x; 1.0396x over previous
#include <cuda_runtime.h>
#include <cuda_fp16.h>
#include <cstdint>
#include <cstddef>

#define Bn 16
#define Tn 2048
#define Dn 1024
#define Hn 512
#define Mn (Bn*Tn)      // 32768
#define Nn 3072
#define Kn 1024

// scratch (static __device__ arrays: allocation-free)
__device__ __half g_Wt[(size_t)Nn * Kn];  // [n'][k], n' = plane*1024 + z*512 + h  (fp16)
__device__ __half g_xh[(size_t)Mn * Kn];  // x in fp16
__device__ float  g_U [(size_t)Mn * Nn];  // [m][n'],  m = b*T + t

// ------------------------------- helpers -------------------------------
__device__ __forceinline__ uint32_t smem_u32(const void* p) {
    uint32_t a;
    asm("{ .reg .u64 t; cvta.to.shared.u64 t, %1; cvt.u32.u64 %0, t; }" : "=r"(a) : "l"(p));
    return a;
}

#define SWZ(o) ((o) ^ (((o) >> 3) & 0x70))

__device__ __forceinline__ void cp_async16(uint32_t saddr, const void* gptr) {
    asm volatile("cp.async.cg.shared.global [%0], [%1], 16;" :: "r"(saddr), "l"(gptr) : "memory");
}
__device__ __forceinline__ void cp_commit() {
    asm volatile("cp.async.commit_group;" ::: "memory");
}
template<int N> __device__ __forceinline__ void cp_wait() {
    asm volatile("cp.async.wait_group %0;" :: "n"(N) : "memory");
}

#define LDSM4(r, addr) \
    asm volatile("ldmatrix.sync.aligned.m8n8.x4.shared.b16 {%0,%1,%2,%3}, [%4];" \
        : "=r"((r)[0]), "=r"((r)[1]), "=r"((r)[2]), "=r"((r)[3]) : "r"(addr))

#define MMA_F16(d, a, b) \
    asm volatile("mma.sync.aligned.m16n8k16.row.col.f32.f16.f16.f32 " \
        "{%0,%1,%2,%3}, {%4,%5,%6,%7}, {%8,%9}, {%0,%1,%2,%3};" \
        : "+f"((d)[0]), "+f"((d)[1]), "+f"((d)[2]), "+f"((d)[3]) \
        : "r"((a)[0]), "r"((a)[1]), "r"((a)[2]), "r"((a)[3]), "r"((b)[0]), "r"((b)[1]))

// ------------------------- Kernel 0a: x -> fp16 -------------------------
__global__ void __launch_bounds__(256) sru_xh(const float* __restrict__ x) {
    size_t i = (size_t)blockIdx.x * 256 + threadIdx.x;
    float4 v = ((const float4*)x)[i];
    __half2* o = (__half2*)g_xh + i * 2;
    o[0] = __floats2half2_rn(v.x, v.y);
    o[1] = __floats2half2_rn(v.z, v.w);
}

// ------------------------- Kernel 0b: W repack (tiled transpose, fp16) -------------------------
__global__ void __launch_bounds__(256) sru_wt(const float* __restrict__ W) {
    __shared__ float tile[32][33];
    const int tx = threadIdx.x, ty = threadIdx.y;   // 32 x 8
    const int zh0 = blockIdx.x * 32;
    const int d0  = blockIdx.y * 32;
    const int kk  = blockIdx.z;
    #pragma unroll
    for (int r = 0; r < 4; r++) {
        int d = d0 + ty + r * 8;
        int zh = zh0 + tx;
        tile[ty + r * 8][tx] = W[(size_t)d * 3072 + zh * 3 + kk];
    }
    __syncthreads();
    #pragma unroll
    for (int r = 0; r < 4; r++) {
        int zh = zh0 + ty + r * 8;
        int d  = d0 + tx;
        g_Wt[(size_t)(kk * 1024 + zh) * 1024 + d] = __float2half_rn(tile[tx][ty + r * 8]);
    }
}

// ------------------------- Kernel 1: fp16 mma.sync GEMM (fp32 accum) -------------------------
#define BM 128
#define BN 256
#define BK 64
#define NCHUNK (Kn / BK)            // 16
#define ASZ (BM * 128)              // 16384 bytes
#define BSZ (BN * 128)              // 32768 bytes
#define STGB (ASZ + BSZ)            // 49152
#define STAGES 4
#define SMEM_TOTAL (STAGES * STGB)  // 196608

__global__ void __launch_bounds__(256, 1) sru_gemm() {
    extern __shared__ __align__(1024) char smem[];
    const uint32_t sb = smem_u32(smem);
    const int tid = threadIdx.x;
    const int lane = tid & 31;
    const int w = tid >> 5;                 // 0..7
    const int m0 = blockIdx.y * BM;
    const int n0 = blockIdx.x * BN;
    const int wm = (w & 1) * 64;
    const int wn = (w >> 1) * 64;

    const int rr  = tid >> 3;   // 0..31
    const int seg = tid & 7;    // 0..7
    const __half* aS = g_xh + (size_t)(m0 + rr) * Kn + seg * 8;
    const __half* bS = g_Wt + (size_t)(n0 + rr) * Kn + seg * 8;
    uint32_t aO[4], bO[8];
    #pragma unroll
    for (int j = 0; j < 4; j++) { uint32_t o = (uint32_t)(rr + 32 * j) * 128 + seg * 16; aO[j] = SWZ(o); }
    #pragma unroll
    for (int j = 0; j < 8; j++) { uint32_t o = (uint32_t)(rr + 32 * j) * 128 + seg * 16; bO[j] = ASZ + SWZ(o); }

    auto ldchunk = [&](int c, int s) {
        uint32_t st = sb + (uint32_t)s * STGB;
        const __half* ap = aS + c * BK;
        const __half* bp = bS + c * BK;
        #pragma unroll
        for (int j = 0; j < 4; j++) cp_async16(st + aO[j], ap + (size_t)(32 * j) * Kn);
        #pragma unroll
        for (int j = 0; j < 8; j++) cp_async16(st + bO[j], bp + (size_t)(32 * j) * Kn);
        cp_commit();
    };

    uint32_t aRow[4], aXor[4];
    #pragma unroll
    for (int mi = 0; mi < 4; mi++) {
        uint32_t r = wm + mi * 16 + ((lane & 8) ? 8 : 0) + (lane & 7);
        aRow[mi] = r * 128; aXor[mi] = (r & 7) << 4;
    }
    const uint32_t aHi = (lane & 16) ? 16 : 0;
    uint32_t bRow[4], bXor[4];
    #pragma unroll
    for (int p = 0; p < 4; p++) {
        uint32_t r = wn + p * 16 + ((lane & 16) ? 8 : 0) + (lane & 7);
        bRow[p] = ASZ + r * 128; bXor[p] = (r & 7) << 4;
    }
    const uint32_t bHi = (lane & 8) ? 16 : 0;

    float acc[4][8][4];
    #pragma unroll
    for (int mi = 0; mi < 4; mi++)
        #pragma unroll
        for (int nj = 0; nj < 8; nj++)
            #pragma unroll
            for (int q = 0; q < 4; q++) acc[mi][nj][q] = 0.f;

    ldchunk(0, 0);
    ldchunk(1, 1);

    for (int i = 0; i < NCHUNK; i++) {
        if (i + 2 < NCHUNK) ldchunk(i + 2, (i + 2) & 3);
        else                cp_commit();
        cp_wait<2>();
        __syncthreads();

        uint32_t st = sb + (uint32_t)(i & 3) * STGB;
        #pragma unroll
        for (int ks = 0; ks < 4; ks++) {
            uint32_t koff = ks * 32;
            uint32_t ar[4][4], br[4][4];
            #pragma unroll
            for (int mi = 0; mi < 4; mi++)
                LDSM4(ar[mi], st + aRow[mi] + ((koff + aHi) ^ aXor[mi]));
            #pragma unroll
            for (int p = 0; p < 4; p++)
                LDSM4(br[p], st + bRow[p] + ((koff + bHi) ^ bXor[p]));
            #pragma unroll
            for (int mi = 0; mi < 4; mi++)
                #pragma unroll
                for (int nj = 0; nj < 8; nj++)
                    MMA_F16(acc[mi][nj], ar[mi], &br[nj >> 1][(nj & 1) * 2]);
        }
    }

    const int rowb = m0 + wm + (lane >> 2);
    const int colb = n0 + wn + (lane & 3) * 2;
    #pragma unroll
    for (int mi = 0; mi < 4; mi++)
        #pragma unroll
        for (int nj = 0; nj < 8; nj++) {
            size_t base = (size_t)(rowb + mi * 16) * Nn + colb + nj * 8;
            float2 v0 = make_float2(acc[mi][nj][0], acc[mi][nj][1]);
            float2 v1 = make_float2(acc[mi][nj][2], acc[mi][nj][3]);
            *(float2*)(g_U + base) = v0;
            *(float2*)(g_U + base + 8 * (size_t)Nn) = v1;
        }
}

// ------------------------- Kernel 2: SRU scan, warp shfl-scan over time -------------------------
// Block: 1024 threads = 32 warps. Block handles one (b,z) and 32 h-channels; warp w owns h0+w.
// Per tile: 32 timesteps. Lane = position in scan order. Kogge-Stone inclusive scan of
// the affine recurrence c' = a*c + b with (a,b) = (f, (1-f)*g).
#define NT (Tn / 32)    // 64 tiles

__global__ void __launch_bounds__(1024, 1) sru_scan(const float* __restrict__ x,
                                                    const float* __restrict__ bias,
                                                    float* __restrict__ out) {
    __shared__ float sbuf[4][32][33];   // g,f,r,x tiles [trow][h]
    __shared__ float obuf[32][33];

    const int tid = threadIdx.x;
    const int lane = tid & 31;
    const int w = tid >> 5;             // warp = h channel
    const int bx = blockIdx.x;          // 512 blocks
    const int hg = bx & 15;
    const int z  = (bx >> 4) & 1;
    const int b  = bx >> 5;
    const int h0 = hg * 32;
    const int fwd = (z == 0);

    const float bf = bias[z * 1024 + h0 + w];
    const float br = bias[z * 1024 + 512 + h0 + w];

    // load mapping: a = tid>>8 (0..3), u = tid&255: hh = u&31, r0 = u>>5 (rows r0+8j)
    const int a  = tid >> 8;
    const int hh = tid & 31;
    const int r0 = (tid >> 5) & 7;
    const float* pa;
    long stride;
    if (a < 3) { pa = g_U + (size_t)b * Tn * Nn + z * 512 + h0 + hh + (size_t)a * 1024; stride = Nn; }
    else       { pa = x   + (size_t)b * Tn * Dn + z * 512 + h0 + hh;                    stride = Dn; }

    float rv[4];
    auto load_tile = [&](int it) {
        long t0 = fwd ? (long)it * 32 : (long)(NT - 1 - it) * 32;
        #pragma unroll
        for (int j = 0; j < 4; j++)
            rv[j] = pa[(t0 + r0 + 8 * j) * stride];
    };

    load_tile(0);
    float carry = 0.f;
    const int row = fwd ? lane : 31 - lane;     // smem row for this lane's timestep

    for (int it = 0; it < NT; it++) {
        // stage regs -> smem
        #pragma unroll
        for (int j = 0; j < 4; j++)
            sbuf[a][r0 + 8 * j][hh] = rv[j];
        __syncthreads();
        if (it + 1 < NT) load_tile(it + 1);     // prefetch (LDGs overlap compute)

        // compute: this warp's channel, 32 timesteps
        float G  = sbuf[0][row][w];
        float F  = sbuf[1][row][w];
        float R  = sbuf[2][row][w];
        float Xv = sbuf[3][row][w];

        float fv = __fdividef(1.f, 1.f + __expf(-(F + bf)));
        float aa = fv;
        float bb = (1.f - fv) * G;
        #pragma unroll
        for (int d = 1; d < 32; d <<= 1) {
            float ap = __shfl_up_sync(0xFFFFFFFFu, aa, d);
            float bp = __shfl_up_sync(0xFFFFFFFFu, bb, d);
            if (lane >= d) { bb = fmaf(aa, bp, bb); aa *= ap; }
        }
        float c = fmaf(aa, carry, bb);
        carry = __shfl_sync(0xFFFFFFFFu, c, 31);

        float rr2 = __fdividef(1.f, 1.f + __expf(-(R + br)));
        float eT = __expf(2.f * c);
        float th = 1.f - 2.f * __fdividef(1.f, 1.f + eT);
        obuf[row][w] = fmaf(rr2, th - Xv, Xv);
        __syncthreads();

        // coalesced store of out tile
        {
            long t0 = fwd ? (long)it * 32 : (long)(NT - 1 - it) * 32;
            int tr = tid >> 5;      // 0..31
            out[((size_t)b * Tn + t0 + tr) * Dn + z * 512 + h0 + (tid & 31)] = obuf[tr][tid & 31];
        }
    }

    // c_last: (B, 1, 2H) appended after out
    if (lane == 0)
        out[(size_t)Bn * Tn * Dn + (size_t)b * 1024 + z * 512 + h0 + w] = carry;
}

// ------------------------------- launch -------------------------------
extern "C" void kernel_launch(void* const* d_in, const int* in_sizes, int n_in,
                              void* d_out, int out_size) {
    const float* x    = (const float*)d_in[0];
    const float* W    = (const float*)d_in[1];
    const float* bias = (const float*)d_in[2];
    float* out = (float*)d_out;
    (void)in_sizes; (void)n_in; (void)out_size;

    cudaFuncSetAttribute(sru_gemm, cudaFuncAttributeMaxDynamicSharedMemorySize, SMEM_TOTAL);

    sru_xh  <<<(Mn * (Kn / 4)) / 256, 256>>>(x);
    sru_wt  <<<dim3(32, 32, 3), dim3(32, 8)>>>(W);
    sru_gemm<<<dim3(Nn / BN, Mn / BM), 256, SMEM_TOTAL>>>();
    sru_scan<<<512, 1024>>>(x, bias, out);
}

// round 7
// speedup vs baseline: 1.8745x; 1.1541x over previous
#include <cuda_runtime.h>
#include <cuda_fp16.h>
#include <cstdint>
#include <cstddef>

#define Bn 16
#define Tn 2048
#define Dn 1024
#define Hn 512
#define Mn (Bn*Tn)      // 32768
#define Nn 3072
#define Kn 1024

// scratch (static __device__ arrays: allocation-free)
__device__ __half g_Wt[(size_t)Nn * Kn];  // [n'][k], n' = plane*1024 + z*512 + h  (fp16)
__device__ __half g_xh[(size_t)Mn * Kn];  // x in fp16
__device__ __half g_Uh[(size_t)Mn * Nn];  // U in fp16: [m][n'], m = b*T + t

// ------------------------------- helpers -------------------------------
__device__ __forceinline__ uint32_t smem_u32(const void* p) {
    uint32_t a;
    asm("{ .reg .u64 t; cvta.to.shared.u64 t, %1; cvt.u32.u64 %0, t; }" : "=r"(a) : "l"(p));
    return a;
}

#define SWZ(o) ((o) ^ (((o) >> 3) & 0x70))

__device__ __forceinline__ void cp_async16(uint32_t saddr, const void* gptr) {
    asm volatile("cp.async.cg.shared.global [%0], [%1], 16;" :: "r"(saddr), "l"(gptr) : "memory");
}
__device__ __forceinline__ void cp_commit() {
    asm volatile("cp.async.commit_group;" ::: "memory");
}
template<int N> __device__ __forceinline__ void cp_wait() {
    asm volatile("cp.async.wait_group %0;" :: "n"(N) : "memory");
}

#define LDSM4(r, addr) \
    asm volatile("ldmatrix.sync.aligned.m8n8.x4.shared.b16 {%0,%1,%2,%3}, [%4];" \
        : "=r"((r)[0]), "=r"((r)[1]), "=r"((r)[2]), "=r"((r)[3]) : "r"(addr))

#define MMA_F16(d, a, b) \
    asm volatile("mma.sync.aligned.m16n8k16.row.col.f32.f16.f16.f32 " \
        "{%0,%1,%2,%3}, {%4,%5,%6,%7}, {%8,%9}, {%0,%1,%2,%3};" \
        : "+f"((d)[0]), "+f"((d)[1]), "+f"((d)[2]), "+f"((d)[3]) \
        : "r"((a)[0]), "r"((a)[1]), "r"((a)[2]), "r"((a)[3]), "r"((b)[0]), "r"((b)[1]))

// ------------------------- Kernel 0a: x -> fp16 -------------------------
__global__ void __launch_bounds__(256) sru_xh(const float* __restrict__ x) {
    size_t i = (size_t)blockIdx.x * 256 + threadIdx.x;
    float4 v = ((const float4*)x)[i];
    __half2* o = (__half2*)g_xh + i * 2;
    o[0] = __floats2half2_rn(v.x, v.y);
    o[1] = __floats2half2_rn(v.z, v.w);
}

// ------------------------- Kernel 0b: W repack (tiled transpose, fp16) -------------------------
__global__ void __launch_bounds__(256) sru_wt(const float* __restrict__ W) {
    __shared__ float tile[32][33];
    const int tx = threadIdx.x, ty = threadIdx.y;   // 32 x 8
    const int zh0 = blockIdx.x * 32;
    const int d0  = blockIdx.y * 32;
    const int kk  = blockIdx.z;
    #pragma unroll
    for (int r = 0; r < 4; r++) {
        int d = d0 + ty + r * 8;
        int zh = zh0 + tx;
        tile[ty + r * 8][tx] = W[(size_t)d * 3072 + zh * 3 + kk];
    }
    __syncthreads();
    #pragma unroll
    for (int r = 0; r < 4; r++) {
        int zh = zh0 + ty + r * 8;
        int d  = d0 + tx;
        g_Wt[(size_t)(kk * 1024 + zh) * 1024 + d] = __float2half_rn(tile[tx][ty + r * 8]);
    }
}

// ------------------------- Kernel 1: fp16 mma.sync GEMM (fp32 accum, fp16 out) -------------------------
#define BM 128
#define BN 256
#define BK 64
#define NCHUNK (Kn / BK)            // 16
#define ASZ (BM * 128)              // 16384 bytes
#define BSZ (BN * 128)              // 32768 bytes
#define STGB (ASZ + BSZ)            // 49152
#define STAGES 4
#define SMEM_TOTAL (STAGES * STGB)  // 196608

__global__ void __launch_bounds__(256, 1) sru_gemm() {
    extern __shared__ __align__(1024) char smem[];
    const uint32_t sb = smem_u32(smem);
    const int tid = threadIdx.x;
    const int lane = tid & 31;
    const int w = tid >> 5;                 // 0..7
    const int m0 = blockIdx.y * BM;
    const int n0 = blockIdx.x * BN;
    const int wm = (w & 1) * 64;
    const int wn = (w >> 1) * 64;

    const int rr  = tid >> 3;   // 0..31
    const int seg = tid & 7;    // 0..7
    const __half* aS = g_xh + (size_t)(m0 + rr) * Kn + seg * 8;
    const __half* bS = g_Wt + (size_t)(n0 + rr) * Kn + seg * 8;
    uint32_t aO[4], bO[8];
    #pragma unroll
    for (int j = 0; j < 4; j++) { uint32_t o = (uint32_t)(rr + 32 * j) * 128 + seg * 16; aO[j] = SWZ(o); }
    #pragma unroll
    for (int j = 0; j < 8; j++) { uint32_t o = (uint32_t)(rr + 32 * j) * 128 + seg * 16; bO[j] = ASZ + SWZ(o); }

    auto ldchunk = [&](int c, int s) {
        uint32_t st = sb + (uint32_t)s * STGB;
        const __half* ap = aS + c * BK;
        const __half* bp = bS + c * BK;
        #pragma unroll
        for (int j = 0; j < 4; j++) cp_async16(st + aO[j], ap + (size_t)(32 * j) * Kn);
        #pragma unroll
        for (int j = 0; j < 8; j++) cp_async16(st + bO[j], bp + (size_t)(32 * j) * Kn);
        cp_commit();
    };

    uint32_t aRow[4], aXor[4];
    #pragma unroll
    for (int mi = 0; mi < 4; mi++) {
        uint32_t r = wm + mi * 16 + ((lane & 8) ? 8 : 0) + (lane & 7);
        aRow[mi] = r * 128; aXor[mi] = (r & 7) << 4;
    }
    const uint32_t aHi = (lane & 16) ? 16 : 0;
    uint32_t bRow[4], bXor[4];
    #pragma unroll
    for (int p = 0; p < 4; p++) {
        uint32_t r = wn + p * 16 + ((lane & 16) ? 8 : 0) + (lane & 7);
        bRow[p] = ASZ + r * 128; bXor[p] = (r & 7) << 4;
    }
    const uint32_t bHi = (lane & 8) ? 16 : 0;

    float acc[4][8][4];
    #pragma unroll
    for (int mi = 0; mi < 4; mi++)
        #pragma unroll
        for (int nj = 0; nj < 8; nj++)
            #pragma unroll
            for (int q = 0; q < 4; q++) acc[mi][nj][q] = 0.f;

    ldchunk(0, 0);
    ldchunk(1, 1);

    for (int i = 0; i < NCHUNK; i++) {
        if (i + 2 < NCHUNK) ldchunk(i + 2, (i + 2) & 3);
        else                cp_commit();
        cp_wait<2>();
        __syncthreads();

        uint32_t st = sb + (uint32_t)(i & 3) * STGB;
        #pragma unroll
        for (int ks = 0; ks < 4; ks++) {
            uint32_t koff = ks * 32;
            uint32_t ar[4][4], br[4][4];
            #pragma unroll
            for (int mi = 0; mi < 4; mi++)
                LDSM4(ar[mi], st + aRow[mi] + ((koff + aHi) ^ aXor[mi]));
            #pragma unroll
            for (int p = 0; p < 4; p++)
                LDSM4(br[p], st + bRow[p] + ((koff + bHi) ^ bXor[p]));
            #pragma unroll
            for (int mi = 0; mi < 4; mi++)
                #pragma unroll
                for (int nj = 0; nj < 8; nj++)
                    MMA_F16(acc[mi][nj], ar[mi], &br[nj >> 1][(nj & 1) * 2]);
        }
    }

    // fp16 epilogue
    const int rowb = m0 + wm + (lane >> 2);
    const int colb = n0 + wn + (lane & 3) * 2;
    #pragma unroll
    for (int mi = 0; mi < 4; mi++)
        #pragma unroll
        for (int nj = 0; nj < 8; nj++) {
            size_t base = (size_t)(rowb + mi * 16) * Nn + colb + nj * 8;
            *(__half2*)(g_Uh + base) = __floats2half2_rn(acc[mi][nj][0], acc[mi][nj][1]);
            *(__half2*)(g_Uh + base + 8 * (size_t)Nn) = __floats2half2_rn(acc[mi][nj][2], acc[mi][nj][3]);
        }
}

// ------------------------- Kernel 2: SRU scan, warp shfl-scan, 2 channels/warp -------------------------
// Block: 512 threads = 16 warps; covers one (b,z) and 32 h-channels; warp w owns channels 2w, 2w+1.
// Tiles of 32 timesteps; lane = scan position. Affine recurrence scan via Kogge-Stone.
#define NT (Tn / 32)    // 64 tiles

__global__ void __launch_bounds__(512, 2) sru_scan(const float* __restrict__ x,
                                                   const float* __restrict__ bias,
                                                   float* __restrict__ out) {
    __shared__ __half sbuf[3][32][34];  // g,f,r: [t][ch], stride 34 halfs (17 words, odd -> bank-clean)
    __shared__ float  xbuf[32][33];
    __shared__ float  obuf[32][33];

    const int tid = threadIdx.x;
    const int lane = tid & 31;
    const int w = tid >> 5;             // 0..15
    const int bx = blockIdx.x;          // 512 blocks: hg(16) z(2) b(16)
    const int hg = bx & 15;
    const int z  = (bx >> 4) & 1;
    const int b  = bx >> 5;
    const int h0 = hg * 32;
    const int fwd = (z == 0);
    const int c0 = 2 * w, c1 = 2 * w + 1;

    const float bf0 = bias[z * 1024 + h0 + c0];
    const float bf1 = bias[z * 1024 + h0 + c1];
    const float br0 = bias[z * 1024 + 512 + h0 + c0];
    const float br1 = bias[z * 1024 + 512 + h0 + c1];

    const size_t bT = (size_t)b * Tn;

    // U-loader role (tid<384): plane p, row tU, seg sU (8 halfs)
    const int p  = tid >> 7;
    const int tU = (tid >> 2) & 31;
    const int sU = tid & 3;
    const size_t uoff = (size_t)p * 1024 + z * 512 + h0 + sU * 8;
    // x-loader role (tid>=384): 2 chunks of 4 floats
    const int u = tid - 384;            // 0..127
    const int tX0 = u >> 3,          sX0 = u & 7;
    const int tX1 = (u + 128) >> 3,  sX1 = (u + 128) & 7;

    uint4 ru, rx0, rx1;
    auto load_tile = [&](int it) {
        long t0 = fwd ? (long)it * 32 : (long)(NT - 1 - it) * 32;
        if (tid < 384) {
            ru = *(const uint4*)(g_Uh + (bT + t0 + tU) * Nn + uoff);
        } else {
            rx0 = *(const uint4*)(x + (bT + t0 + tX0) * Dn + z * 512 + h0 + sX0 * 4);
            rx1 = *(const uint4*)(x + (bT + t0 + tX1) * Dn + z * 512 + h0 + sX1 * 4);
        }
    };

    load_tile(0);
    float carry0 = 0.f, carry1 = 0.f;
    const int row = fwd ? lane : 31 - lane;

    for (int it = 0; it < NT; it++) {
        // stage regs -> smem
        if (tid < 384) {
            uint32_t* dst = (uint32_t*)&sbuf[p][tU][sU * 8];
            dst[0] = ru.x; dst[1] = ru.y; dst[2] = ru.z; dst[3] = ru.w;
        } else {
            float* d0 = &xbuf[tX0][sX0 * 4];
            d0[0] = __uint_as_float(rx0.x); d0[1] = __uint_as_float(rx0.y);
            d0[2] = __uint_as_float(rx0.z); d0[3] = __uint_as_float(rx0.w);
            float* d1 = &xbuf[tX1][sX1 * 4];
            d1[0] = __uint_as_float(rx1.x); d1[1] = __uint_as_float(rx1.y);
            d1[2] = __uint_as_float(rx1.z); d1[3] = __uint_as_float(rx1.w);
        }
        __syncthreads();
        if (it + 1 < NT) load_tile(it + 1);     // prefetch overlaps compute

        // compute: 2 channels per warp
        float2 G = __half22float2(*(const __half2*)&sbuf[0][row][c0]);
        float2 F = __half22float2(*(const __half2*)&sbuf[1][row][c0]);
        float2 R = __half22float2(*(const __half2*)&sbuf[2][row][c0]);
        float xv0 = xbuf[row][c0], xv1 = xbuf[row][c1];

        float fv0 = __fdividef(1.f, 1.f + __expf(-(F.x + bf0)));
        float fv1 = __fdividef(1.f, 1.f + __expf(-(F.y + bf1)));
        float a0 = fv0, b0 = (1.f - fv0) * G.x;
        float a1 = fv1, b1 = (1.f - fv1) * G.y;
        #pragma unroll
        for (int d = 1; d < 32; d <<= 1) {
            float ap0 = __shfl_up_sync(0xFFFFFFFFu, a0, d);
            float bp0 = __shfl_up_sync(0xFFFFFFFFu, b0, d);
            float ap1 = __shfl_up_sync(0xFFFFFFFFu, a1, d);
            float bp1 = __shfl_up_sync(0xFFFFFFFFu, b1, d);
            if (lane >= d) {
                b0 = fmaf(a0, bp0, b0); a0 *= ap0;
                b1 = fmaf(a1, bp1, b1); a1 *= ap1;
            }
        }
        float cc0 = fmaf(a0, carry0, b0);
        float cc1 = fmaf(a1, carry1, b1);
        carry0 = __shfl_sync(0xFFFFFFFFu, cc0, 31);
        carry1 = __shfl_sync(0xFFFFFFFFu, cc1, 31);

        float rv0 = __fdividef(1.f, 1.f + __expf(-(R.x + br0)));
        float rv1 = __fdividef(1.f, 1.f + __expf(-(R.y + br1)));
        float th0 = 1.f - 2.f * __fdividef(1.f, 1.f + __expf(2.f * cc0));
        float th1 = 1.f - 2.f * __fdividef(1.f, 1.f + __expf(2.f * cc1));
        obuf[row][c0] = fmaf(rv0, th0 - xv0, xv0);
        obuf[row][c1] = fmaf(rv1, th1 - xv1, xv1);
        __syncthreads();

        // coalesced store of out tile: 512 threads x float2
        {
            long t0 = fwd ? (long)it * 32 : (long)(NT - 1 - it) * 32;
            int tr = tid >> 4;              // 0..31
            int cl = (tid & 15) * 2;
            float2 v = make_float2(obuf[tr][cl], obuf[tr][cl + 1]);
            *(float2*)(out + (bT + t0 + tr) * Dn + z * 512 + h0 + cl) = v;
        }
    }

    // c_last: (B, 1, 2H) appended after out
    if (lane == 0) {
        out[(size_t)Bn * Tn * Dn + (size_t)b * 1024 + z * 512 + h0 + c0] = carry0;
        out[(size_t)Bn * Tn * Dn + (size_t)b * 1024 + z * 512 + h0 + c1] = carry1;
    }
}

// ------------------------------- launch -------------------------------
extern "C" void kernel_launch(void* const* d_in, const int* in_sizes, int n_in,
                              void* d_out, int out_size) {
    const float* x    = (const float*)d_in[0];
    const float* W    = (const float*)d_in[1];
    const float* bias = (const float*)d_in[2];
    float* out = (float*)d_out;
    (void)in_sizes; (void)n_in; (void)out_size;

    cudaFuncSetAttribute(sru_gemm, cudaFuncAttributeMaxDynamicSharedMemorySize, SMEM_TOTAL);

    sru_xh  <<<(Mn * (Kn / 4)) / 256, 256>>>(x);
    sru_wt  <<<dim3(32, 32, 3), dim3(32, 8)>>>(W);
    sru_gemm<<<dim3(Nn / BN, Mn / BM), 256, SMEM_TOTAL>>>();
    sru_scan<<<512, 512>>>(x, bias, out);
}

// round 8
// speedup vs baseline: 2.0196x; 1.0774x over previous
#include <cuda_runtime.h>
#include <cuda_fp16.h>
#include <cstdint>
#include <cstddef>

#define Bn 16
#define Tn 2048
#define Dn 1024
#define Hn 512
#define Mn (Bn*Tn)      // 32768
#define Nn 3072
#define Kn 1024

// scratch (static __device__ arrays: allocation-free)
__device__ __half g_Wt[(size_t)Nn * Kn];  // [n'][k], n' = plane*1024 + z*512 + h  (fp16)
__device__ __half g_xh[(size_t)Mn * Kn];  // x in fp16
__device__ __half g_Uh[(size_t)Mn * Nn];  // U in fp16: [m][n'], m = b*T + t

// ------------------------------- helpers -------------------------------
__device__ __forceinline__ uint32_t smem_u32(const void* p) {
    uint32_t a;
    asm("{ .reg .u64 t; cvta.to.shared.u64 t, %1; cvt.u32.u64 %0, t; }" : "=r"(a) : "l"(p));
    return a;
}

#define SWZ(o) ((o) ^ (((o) >> 3) & 0x70))

__device__ __forceinline__ void cp_async16(uint32_t saddr, const void* gptr) {
    asm volatile("cp.async.cg.shared.global [%0], [%1], 16;" :: "r"(saddr), "l"(gptr) : "memory");
}
__device__ __forceinline__ void cp_commit() {
    asm volatile("cp.async.commit_group;" ::: "memory");
}
template<int N> __device__ __forceinline__ void cp_wait() {
    asm volatile("cp.async.wait_group %0;" :: "n"(N) : "memory");
}

#define LDSM4(r, addr) \
    asm volatile("ldmatrix.sync.aligned.m8n8.x4.shared.b16 {%0,%1,%2,%3}, [%4];" \
        : "=r"((r)[0]), "=r"((r)[1]), "=r"((r)[2]), "=r"((r)[3]) : "r"(addr))

#define MMA_F16(d, a, b) \
    asm volatile("mma.sync.aligned.m16n8k16.row.col.f32.f16.f16.f32 " \
        "{%0,%1,%2,%3}, {%4,%5,%6,%7}, {%8,%9}, {%0,%1,%2,%3};" \
        : "+f"((d)[0]), "+f"((d)[1]), "+f"((d)[2]), "+f"((d)[3]) \
        : "r"((a)[0]), "r"((a)[1]), "r"((a)[2]), "r"((a)[3]), "r"((b)[0]), "r"((b)[1]))

// ------------------------- Kernel 0a: x -> fp16 -------------------------
__global__ void __launch_bounds__(256) sru_xh(const float* __restrict__ x) {
    size_t i = (size_t)blockIdx.x * 256 + threadIdx.x;
    float4 v = ((const float4*)x)[i];
    __half2* o = (__half2*)g_xh + i * 2;
    o[0] = __floats2half2_rn(v.x, v.y);
    o[1] = __floats2half2_rn(v.z, v.w);
}

// ------------------------- Kernel 0b: W repack (tiled transpose, fp16) -------------------------
__global__ void __launch_bounds__(256) sru_wt(const float* __restrict__ W) {
    __shared__ float tile[32][33];
    const int tx = threadIdx.x, ty = threadIdx.y;   // 32 x 8
    const int zh0 = blockIdx.x * 32;
    const int d0  = blockIdx.y * 32;
    const int kk  = blockIdx.z;
    #pragma unroll
    for (int r = 0; r < 4; r++) {
        int d = d0 + ty + r * 8;
        int zh = zh0 + tx;
        tile[ty + r * 8][tx] = W[(size_t)d * 3072 + zh * 3 + kk];
    }
    __syncthreads();
    #pragma unroll
    for (int r = 0; r < 4; r++) {
        int zh = zh0 + ty + r * 8;
        int d  = d0 + tx;
        g_Wt[(size_t)(kk * 1024 + zh) * 1024 + d] = __float2half_rn(tile[tx][ty + r * 8]);
    }
}

// ------------------------- Kernel 1: fp16 mma.sync GEMM, 128x128 tiles, 2 CTAs/SM -------------------------
#define BM 128
#define BN 128
#define BK 64
#define NCHUNK (Kn / BK)            // 16
#define ASZ (BM * 128)              // 16384 bytes
#define BSZ (BN * 128)              // 16384 bytes
#define STGB (ASZ + BSZ)            // 32768
#define STAGES 3
#define SMEM_TOTAL (STAGES * STGB)  // 98304

__global__ void __launch_bounds__(256, 2) sru_gemm() {
    extern __shared__ __align__(1024) char smem[];
    const uint32_t sb = smem_u32(smem);
    const int tid = threadIdx.x;
    const int lane = tid & 31;
    const int w = tid >> 5;                 // 0..7
    const int m0 = blockIdx.y * BM;
    const int n0 = blockIdx.x * BN;
    const int wm = (w & 3) * 32;            // 4 m-warps
    const int wn = (w >> 2) * 64;           // 2 n-warps

    // cp.async geometry: 16B segs; rows rr+32j (j<4) for A and B
    const int rr  = tid >> 3;   // 0..31
    const int seg = tid & 7;    // 0..7
    const __half* aS = g_xh + (size_t)(m0 + rr) * Kn + seg * 8;
    const __half* bS = g_Wt + (size_t)(n0 + rr) * Kn + seg * 8;
    uint32_t aO[4], bO[4];
    #pragma unroll
    for (int j = 0; j < 4; j++) {
        uint32_t o = (uint32_t)(rr + 32 * j) * 128 + seg * 16;
        aO[j] = SWZ(o);
        bO[j] = ASZ + SWZ(o);
    }

    auto ldchunk = [&](int c, int s) {
        uint32_t st = sb + (uint32_t)s * STGB;
        const __half* ap = aS + c * BK;
        const __half* bp = bS + c * BK;
        #pragma unroll
        for (int j = 0; j < 4; j++) cp_async16(st + aO[j], ap + (size_t)(32 * j) * Kn);
        #pragma unroll
        for (int j = 0; j < 4; j++) cp_async16(st + bO[j], bp + (size_t)(32 * j) * Kn);
        cp_commit();
    };

    uint32_t aRow[2], aXor[2];
    #pragma unroll
    for (int mi = 0; mi < 2; mi++) {
        uint32_t r = wm + mi * 16 + ((lane & 8) ? 8 : 0) + (lane & 7);
        aRow[mi] = r * 128; aXor[mi] = (r & 7) << 4;
    }
    const uint32_t aHi = (lane & 16) ? 16 : 0;
    uint32_t bRow[4], bXor[4];
    #pragma unroll
    for (int p = 0; p < 4; p++) {
        uint32_t r = wn + p * 16 + ((lane & 16) ? 8 : 0) + (lane & 7);
        bRow[p] = ASZ + r * 128; bXor[p] = (r & 7) << 4;
    }
    const uint32_t bHi = (lane & 8) ? 16 : 0;

    float acc[2][8][4];
    #pragma unroll
    for (int mi = 0; mi < 2; mi++)
        #pragma unroll
        for (int nj = 0; nj < 8; nj++)
            #pragma unroll
            for (int q = 0; q < 4; q++) acc[mi][nj][q] = 0.f;

    ldchunk(0, 0);
    ldchunk(1, 1);

    for (int i = 0; i < NCHUNK; i++) {
        int s = i % 3;
        if (i + 2 < NCHUNK) ldchunk(i + 2, (i + 2) % 3);
        if (i < NCHUNK - 2)       cp_wait<2>();
        else if (i == NCHUNK - 2) cp_wait<1>();
        else                      cp_wait<0>();
        __syncthreads();

        uint32_t st = sb + (uint32_t)s * STGB;
        #pragma unroll
        for (int ks = 0; ks < 4; ks++) {
            uint32_t koff = ks * 32;
            uint32_t ar[2][4], br[4][4];
            #pragma unroll
            for (int mi = 0; mi < 2; mi++)
                LDSM4(ar[mi], st + aRow[mi] + ((koff + aHi) ^ aXor[mi]));
            #pragma unroll
            for (int p = 0; p < 4; p++)
                LDSM4(br[p], st + bRow[p] + ((koff + bHi) ^ bXor[p]));
            #pragma unroll
            for (int mi = 0; mi < 2; mi++)
                #pragma unroll
                for (int nj = 0; nj < 8; nj++)
                    MMA_F16(acc[mi][nj], ar[mi], &br[nj >> 1][(nj & 1) * 2]);
        }
        __syncthreads();
    }

    // fp16 epilogue
    const int rowb = m0 + wm + (lane >> 2);
    const int colb = n0 + wn + (lane & 3) * 2;
    #pragma unroll
    for (int mi = 0; mi < 2; mi++)
        #pragma unroll
        for (int nj = 0; nj < 8; nj++) {
            size_t base = (size_t)(rowb + mi * 16) * Nn + colb + nj * 8;
            *(__half2*)(g_Uh + base) = __floats2half2_rn(acc[mi][nj][0], acc[mi][nj][1]);
            *(__half2*)(g_Uh + base + 8 * (size_t)Nn) = __floats2half2_rn(acc[mi][nj][2], acc[mi][nj][3]);
        }
}

// ------------------------- Kernel 2: SRU scan, 64 steps/tile (2 per lane), 2 ch/warp -------------------------
// Block: 512 threads = 16 warps; one (b,z) and 32 h-channels; warp w owns channels 2w, 2w+1.
// Lane l covers timesteps 2l, 2l+1 of the 64-step tile: local affine compose, pair K-S scan, fix-up.
#define NT64 (Tn / 64)    // 32 tiles

__global__ void __launch_bounds__(512, 2) sru_scan(const float* __restrict__ x,
                                                   const float* __restrict__ bias,
                                                   float* __restrict__ out) {
    __shared__ __half sbuf[3][64][34];  // g,f,r tiles [t][ch]
    __shared__ float  xbuf[64][33];
    __shared__ float  obuf[64][33];

    const int tid = threadIdx.x;
    const int lane = tid & 31;
    const int w = tid >> 5;             // 0..15
    const int bx = blockIdx.x;          // 512 blocks: hg(16) z(2) b(16)
    const int hg = bx & 15;
    const int z  = (bx >> 4) & 1;
    const int b  = bx >> 5;
    const int h0 = hg * 32;
    const int fwd = (z == 0);
    const int c0 = 2 * w, c1 = 2 * w + 1;

    const float bf0 = bias[z * 1024 + h0 + c0];
    const float bf1 = bias[z * 1024 + h0 + c1];
    const float br0 = bias[z * 1024 + 512 + h0 + c0];
    const float br1 = bias[z * 1024 + 512 + h0 + c1];

    const size_t bT = (size_t)b * Tn;

    // U loaders (tid<384): 2 x uint4; q = tid + 384*j -> plane q>>8, t (q&255)>>2, seg q&3
    // x loaders (tid>=384): 4 x float4; idx = (tid-384) + 128*j -> t idx>>3, seg idx&7
    uint4 ru[2], rx[4];
    auto load_tile = [&](int it) {
        long t0 = fwd ? (long)it * 64 : (long)(NT64 - 1 - it) * 64;
        if (tid < 384) {
            #pragma unroll
            for (int j = 0; j < 2; j++) {
                int q = tid + 384 * j;
                int p = q >> 8, rem = q & 255;
                int t = rem >> 2, sg = rem & 3;
                ru[j] = *(const uint4*)(g_Uh + (bT + t0 + t) * Nn + (size_t)p * 1024 + z * 512 + h0 + sg * 8);
            }
        } else {
            #pragma unroll
            for (int j = 0; j < 4; j++) {
                int idx = (tid - 384) + 128 * j;
                int t = idx >> 3, sg = idx & 7;
                rx[j] = *(const uint4*)(x + (bT + t0 + t) * Dn + z * 512 + h0 + sg * 4);
            }
        }
    };

    load_tile(0);
    float carry0 = 0.f, carry1 = 0.f;
    // smem rows for this lane's two timesteps (forward scan order)
    const int pos0 = 2 * lane, pos1 = 2 * lane + 1;
    const int row0 = fwd ? pos0 : 63 - pos0;
    const int row1 = fwd ? pos1 : 63 - pos1;

    for (int it = 0; it < NT64; it++) {
        // stage regs -> smem
        if (tid < 384) {
            #pragma unroll
            for (int j = 0; j < 2; j++) {
                int q = tid + 384 * j;
                int p = q >> 8, rem = q & 255;
                int t = rem >> 2, sg = rem & 3;
                uint32_t* dst = (uint32_t*)&sbuf[p][t][sg * 8];
                dst[0] = ru[j].x; dst[1] = ru[j].y; dst[2] = ru[j].z; dst[3] = ru[j].w;
            }
        } else {
            #pragma unroll
            for (int j = 0; j < 4; j++) {
                int idx = (tid - 384) + 128 * j;
                int t = idx >> 3, sg = idx & 7;
                float* d = &xbuf[t][sg * 4];
                d[0] = __uint_as_float(rx[j].x); d[1] = __uint_as_float(rx[j].y);
                d[2] = __uint_as_float(rx[j].z); d[3] = __uint_as_float(rx[j].w);
            }
        }
        __syncthreads();
        if (it + 1 < NT64) load_tile(it + 1);   // prefetch overlaps compute

        // read 2 timesteps x 2 channels
        float2 Ga = __half22float2(*(const __half2*)&sbuf[0][row0][c0]);
        float2 Fa = __half22float2(*(const __half2*)&sbuf[1][row0][c0]);
        float2 Ra = __half22float2(*(const __half2*)&sbuf[2][row0][c0]);
        float2 Gb = __half22float2(*(const __half2*)&sbuf[0][row1][c0]);
        float2 Fb = __half22float2(*(const __half2*)&sbuf[1][row1][c0]);
        float2 Rb = __half22float2(*(const __half2*)&sbuf[2][row1][c0]);
        float xa0 = xbuf[row0][c0], xa1 = xbuf[row0][c1];
        float xb0 = xbuf[row1][c0], xb1 = xbuf[row1][c1];

        // per-step affine coeffs: c' = a*c + b
        float a00 = __fdividef(1.f, 1.f + __expf(-(Fa.x + bf0)));   // ch0 step0
        float a01 = __fdividef(1.f, 1.f + __expf(-(Fb.x + bf0)));   // ch0 step1
        float a10 = __fdividef(1.f, 1.f + __expf(-(Fa.y + bf1)));   // ch1 step0
        float a11 = __fdividef(1.f, 1.f + __expf(-(Fb.y + bf1)));   // ch1 step1
        float b00 = (1.f - a00) * Ga.x;
        float b01 = (1.f - a01) * Gb.x;
        float b10 = (1.f - a10) * Ga.y;
        float b11 = (1.f - a11) * Gb.y;

        // local pair compose (step0 then step1)
        float A0 = a01 * a00, B0 = fmaf(a01, b00, b01);
        float A1 = a11 * a10, B1 = fmaf(a11, b10, b11);

        // Kogge-Stone inclusive scan over pairs, 2 channels interleaved
        #pragma unroll
        for (int d = 1; d < 32; d <<= 1) {
            float Ap0 = __shfl_up_sync(0xFFFFFFFFu, A0, d);
            float Bp0 = __shfl_up_sync(0xFFFFFFFFu, B0, d);
            float Ap1 = __shfl_up_sync(0xFFFFFFFFu, A1, d);
            float Bp1 = __shfl_up_sync(0xFFFFFFFFu, B1, d);
            if (lane >= d) {
                B0 = fmaf(A0, Bp0, B0); A0 *= Ap0;
                B1 = fmaf(A1, Bp1, B1); A1 *= Ap1;
            }
        }
        // exclusive prefix for this lane
        float Ae0 = __shfl_up_sync(0xFFFFFFFFu, A0, 1);
        float Be0 = __shfl_up_sync(0xFFFFFFFFu, B0, 1);
        float Ae1 = __shfl_up_sync(0xFFFFFFFFu, A1, 1);
        float Be1 = __shfl_up_sync(0xFFFFFFFFu, B1, 1);
        if (lane == 0) { Ae0 = 1.f; Be0 = 0.f; Ae1 = 1.f; Be1 = 0.f; }
        float cin0 = fmaf(Ae0, carry0, Be0);
        float cin1 = fmaf(Ae1, carry1, Be1);
        float ca0 = fmaf(a00, cin0, b00);       // ch0, step0
        float cb0 = fmaf(a01, ca0,  b01);       // ch0, step1
        float ca1 = fmaf(a10, cin1, b10);       // ch1, step0
        float cb1 = fmaf(a11, ca1,  b11);       // ch1, step1
        float At0 = __shfl_sync(0xFFFFFFFFu, A0, 31);
        float Bt0 = __shfl_sync(0xFFFFFFFFu, B0, 31);
        float At1 = __shfl_sync(0xFFFFFFFFu, A1, 31);
        float Bt1 = __shfl_sync(0xFFFFFFFFu, B1, 31);
        carry0 = fmaf(At0, carry0, Bt0);
        carry1 = fmaf(At1, carry1, Bt1);

        // h = r*tanh(c) + (1-r)*x
        float rva0 = __fdividef(1.f, 1.f + __expf(-(Ra.x + br0)));
        float rvb0 = __fdividef(1.f, 1.f + __expf(-(Rb.x + br0)));
        float rva1 = __fdividef(1.f, 1.f + __expf(-(Ra.y + br1)));
        float rvb1 = __fdividef(1.f, 1.f + __expf(-(Rb.y + br1)));
        float tha0 = 1.f - 2.f * __fdividef(1.f, 1.f + __expf(2.f * ca0));
        float thb0 = 1.f - 2.f * __fdividef(1.f, 1.f + __expf(2.f * cb0));
        float tha1 = 1.f - 2.f * __fdividef(1.f, 1.f + __expf(2.f * ca1));
        float thb1 = 1.f - 2.f * __fdividef(1.f, 1.f + __expf(2.f * cb1));
        obuf[row0][c0] = fmaf(rva0, tha0 - xa0, xa0);
        obuf[row1][c0] = fmaf(rvb0, thb0 - xb0, xb0);
        obuf[row0][c1] = fmaf(rva1, tha1 - xa1, xa1);
        obuf[row1][c1] = fmaf(rvb1, thb1 - xb1, xb1);
        __syncthreads();

        // coalesced store: 512 threads x float4 (64 rows x 8 float4)
        {
            long t0 = fwd ? (long)it * 64 : (long)(NT64 - 1 - it) * 64;
            int t = tid >> 3, sg = tid & 7;
            float4 v = make_float4(obuf[t][sg * 4], obuf[t][sg * 4 + 1],
                                   obuf[t][sg * 4 + 2], obuf[t][sg * 4 + 3]);
            *(float4*)(out + (bT + t0 + t) * Dn + z * 512 + h0 + sg * 4) = v;
        }
    }

    // c_last: (B, 1, 2H) appended after out
    if (lane == 0) {
        out[(size_t)Bn * Tn * Dn + (size_t)b * 1024 + z * 512 + h0 + c0] = carry0;
        out[(size_t)Bn * Tn * Dn + (size_t)b * 1024 + z * 512 + h0 + c1] = carry1;
    }
}

// ------------------------------- launch -------------------------------
extern "C" void kernel_launch(void* const* d_in, const int* in_sizes, int n_in,
                              void* d_out, int out_size) {
    const float* x    = (const float*)d_in[0];
    const float* W    = (const float*)d_in[1];
    const float* bias = (const float*)d_in[2];
    float* out = (float*)d_out;
    (void)in_sizes; (void)n_in; (void)out_size;

    cudaFuncSetAttribute(sru_gemm, cudaFuncAttributeMaxDynamicSharedMemorySize, SMEM_TOTAL);

    sru_xh  <<<(Mn * (Kn / 4)) / 256, 256>>>(x);
    sru_wt  <<<dim3(32, 32, 3), dim3(32, 8)>>>(W);
    sru_gemm<<<dim3(Nn / BN, Mn / BM), 256, SMEM_TOTAL>>>();
    sru_scan<<<512, 512>>>(x, bias, out);
}